// round 8
// baseline (speedup 1.0000x reference)
#include <cuda_runtime.h>

#define T_STEPS 2000
#define NB      1024
#define NMUL    16
#define NTH     128   // 4 warps -> SMSPs 0..3
#define NBLK    64    // 64*128 = 8192 threads; 2 lanes per thread = 16384
#define CH      16    // steps per chunk (= conv ring size = unroll)
#define NCHUNK  (T_STEPS / CH)   // 125, exact
#define PF      4     // forcing prefetch depth

__device__ __forceinline__ float fast_lg2(float a) {
    float r;
    asm("lg2.approx.f32 %0, %1;" : "=f"(r) : "f"(a));
    return r;
}
__device__ __forceinline__ float fast_ex2(float a) {
    float r;
    asm("ex2.approx.f32 %0, %1;" : "=f"(r) : "f"(a));
    return r;
}

// One HBV lane: parameters + state, step() returns Qsim.
struct Lane {
    // params
    float BETA, FC, K0, K1, K2, PERC, UZL, TT, CFMAX, CFRCFMAX, CWH, Cpar;
    float invFC, bLP, epsF, CinvFC;
    // state
    float SP, MW, y, SUZ, SLZ;

    __device__ __forceinline__ void init(const float* pb) {
        BETA   = 1.0f   + pb[0*16]  * 5.0f;
        FC     = 50.0f  + pb[1*16]  * 950.0f;
        K0     = 0.05f  + pb[2*16]  * 0.85f;
        K1     = 0.01f  + pb[3*16]  * 0.49f;
        K2     = 0.001f + pb[4*16]  * 0.199f;
        const float LP     = 0.2f + pb[5*16] * 0.8f;
        PERC   =          pb[6*16]  * 10.0f;
        UZL    =          pb[7*16]  * 100.0f;
        TT     = -2.5f  + pb[8*16]  * 5.0f;
        CFMAX  = 0.5f   + pb[9*16]  * 9.5f;
        const float CFR    = pb[10*16] * 0.1f;
        CWH    =          pb[11*16] * 0.2f;
        const float BETAET = 0.3f + pb[12*16] * 4.7f;
        Cpar   =          pb[13*16];
        invFC    = 1.0f / FC;
        bLP      = BETAET * fast_lg2(1.0f / LP);
        epsF     = 1e-5f * invFC;
        CFRCFMAX = CFR * CFMAX;
        CinvFC   = Cpar * invFC;
        SP = 1e-5f; MW = 1e-5f; SUZ = 1e-5f; SLZ = 1e-5f; y = epsF;
        // store BETAET in BETA slot trick not needed; keep BETAET via bLP-only form:
        BETAET_ = BETAET;
    }
    float BETAET_;

    __device__ __forceinline__ float step(float Pm, float Tc, float PE) {
        // snow
        const float rain = (Tc >= TT) ? Pm : 0.0f;
        const float snow = Pm - rain;
        const float m0 = fmaxf(CFMAX * (Tc - TT), 0.0f);
        const float r0 = fmaxf(CFRCFMAX * (TT - Tc), 0.0f);
        SP += snow;
        const float melt = fminf(m0, SP);
        MW += melt;  SP -= melt;
        const float refreeze = fminf(r0, MW);
        SP += refreeze;  MW -= refreeze;
        const float tosoil = fmaxf(fmaf(-CWH, SP, MW), 0.0f);
        MW -= tosoil;
        // soil (y = SM/FC in (0,1])
        const float inr  = rain + tosoil;
        const float inrF = inr * invFC;
        const float yp   = y + inrF;
        const float s    = SLZ * CinvFC;
        const float oms  = 1.0f - s;
        const float sw   = fast_ex2(BETA * fast_lg2(y));   // <=1 by invariant
        const float recharge = inr * sw;
        const float y1 = fmaf(-inrF, sw, yp);
        const float excess = fmaxf(y1 - 1.0f, 0.0f) * FC;
        const float y2 = fminf(y1, 1.0f);
        const float y3 = fmaf(y2, oms, s);                 // capillary fused
        const float cap = SLZ * fmaxf(fmaf(-Cpar, y1, Cpar), 0.0f);
        SLZ -= cap;
        const float ef  = fast_ex2(fminf(fmaf(fast_lg2(y3), BETAET_, bLP), 0.0f));
        const float PEF = PE * invFC;
        y = fmaxf(fmaf(-PEF, ef, y3), epsF);
        // response
        SUZ += recharge + excess;
        const float PERCv = fminf(SUZ, PERC);
        SUZ -= PERCv;
        const float Q0 = K0 * fmaxf(SUZ - UZL, 0.0f);
        SUZ -= Q0;
        const float Q1 = K1 * SUZ;
        SUZ -= Q1;
        SLZ += PERCv;
        const float Q2 = K2 * SLZ;
        SLZ -= Q2;
        return Q0 + Q1 + Q2;
    }
};

__device__ __forceinline__ void make_weights(const float* pb, float* w) {
    const float aa     = fmaxf(pb[256] * 2.9f, 0.0f) + 0.1f;
    const float theta  = fmaxf(pb[272] * 6.5f, 0.0f) + 0.5f;
    const float itheta = 1.0f / theta;
    float wsum = 0.0f;
#pragma unroll
    for (int k = 0; k < 15; ++k) {
        const float tk = (float)k + 0.5f;
        w[k] = expf((aa - 1.0f) * logf(tk) - tk * itheta);
        wsum += w[k];
    }
    const float iws = 1.0f / wsum;
#pragma unroll
    for (int k = 0; k < 15; ++k) w[k] *= iws;
    w[15] = 0.0f;
}

__global__ void __launch_bounds__(NTH, 1)
hbv_kernel(const float* __restrict__ x,      // (T, B, 3)
           const float* __restrict__ ps,     // (B, 288)
           float* __restrict__ out)          // (T, B)
{
    // [warp][cell(4)][m(8)][t(16)+1]: writes conflict-free ((8c+17m)%32 distinct)
    __shared__ float red[4][4][8][17];

    const int w_id = threadIdx.x >> 5;
    const int lane = threadIdx.x & 31;
    const int cell = lane >> 3;        // 0..3
    const int mth  = lane & 7;         // this thread: m = mth and mth+8

    const int gwarp = blockIdx.x * 4 + w_id;
    const int b0    = gwarp * 4;               // warp's first cell
    const int b     = b0 + cell;               // this thread's grid cell

    const float* pbA = ps + b * 288 + mth;     // lane A: m = mth
    const float* pbB = pbA + 8;                // lane B: m = mth+8

    Lane A, B;
    A.init(pbA);
    B.init(pbB);

    float wA[CH], wB[CH];
    make_weights(pbA, wA);
    make_weights(pbB, wB);

    float qA[CH], qB[CH];
#pragma unroll
    for (int k = 0; k < CH; ++k) { qA[k] = 0.0f; qB[k] = 0.0f; }

    // forcing prefetch ring (shared by both lanes: same grid cell b)
    const float* xr = x + (size_t)b * 3;
    float Pf[PF], Tf[PF], Ef[PF];
#pragma unroll
    for (int k = 0; k < PF; ++k) {
        const float* xp = xr + (size_t)k * (NB * 3);
        Pf[k] = __ldg(xp + 0);
        Tf[k] = __ldg(xp + 1);
        Ef[k] = __ldg(xp + 2);
    }

#pragma unroll 1
    for (int c = 0; c < NCHUNK; ++c) {
#pragma unroll
        for (int j = 0; j < CH; ++j) {
            const int t = c * CH + j;
            const int s4 = j & (PF - 1);

            const float Pm = Pf[s4], Tc = Tf[s4], PE = Ef[s4];
            {
                const int tn = (t + PF < T_STEPS) ? (t + PF) : (T_STEPS - 1);
                const float* xp = xr + (size_t)tn * (NB * 3);
                Pf[s4] = __ldg(xp + 0);
                Tf[s4] = __ldg(xp + 1);
                Ef[s4] = __ldg(xp + 2);
            }

            // two independent chains — interleaved by ptxas to fill stalls
            const float QsA = A.step(Pm, Tc, PE);
            const float QsB = B.step(Pm, Tc, PE);

            qA[j] = QsA;
            qB[j] = QsB;
            float a0 = 0.f, a1 = 0.f, a2 = 0.f, a3 = 0.f;
#pragma unroll
            for (int k = 0; k < CH; k += 4) {
                a0 = fmaf(wA[k + 0], qA[(j - k - 0) & 15], a0);
                a1 = fmaf(wA[k + 1], qA[(j - k - 1) & 15], a1);
                a2 = fmaf(wA[k + 2], qA[(j - k - 2) & 15], a2);
                a3 = fmaf(wA[k + 3], qA[(j - k - 3) & 15], a3);
            }
#pragma unroll
            for (int k = 0; k < CH; k += 4) {
                a0 = fmaf(wB[k + 0], qB[(j - k - 0) & 15], a0);
                a1 = fmaf(wB[k + 1], qB[(j - k - 1) & 15], a1);
                a2 = fmaf(wB[k + 2], qB[(j - k - 2) & 15], a2);
                a3 = fmaf(wB[k + 3], qB[(j - k - 3) & 15], a3);
            }
            red[w_id][cell][mth][j] = (a0 + a1) + (a2 + a3);  // QrA+QrB
        }

        // per-chunk transpose reduce: 8 threads' pair-sums -> mean over 16 m
        __syncwarp();
        {
            const int t_o = lane & 15;
#pragma unroll
            for (int io = 0; io < 2; ++io) {
                const int cell_o = (lane >> 4) + 2 * io;    // 0..3
                float s0 = 0.f, s1 = 0.f;
#pragma unroll
                for (int mi = 0; mi < 8; mi += 2) {
                    s0 += red[w_id][cell_o][mi + 0][t_o];
                    s1 += red[w_id][cell_o][mi + 1][t_o];
                }
                out[(c * CH + t_o) * NB + (b0 + cell_o)] = (s0 + s1) * 0.0625f;
            }
        }
        __syncwarp();
    }
}

extern "C" void kernel_launch(void* const* d_in, const int* in_sizes, int n_in,
                              void* d_out, int out_size)
{
    const float* x  = (const float*)d_in[0];
    const float* ps = (const float*)d_in[1];
    if (n_in >= 2 && in_sizes[0] == NB * 288) {  // swapped order
        x  = (const float*)d_in[1];
        ps = (const float*)d_in[0];
    }
    float* out = (float*)d_out;
    hbv_kernel<<<NBLK, NTH>>>(x, ps, out);
}

// round 9
// speedup vs baseline: 1.7311x; 1.7311x over previous
#include <cuda_runtime.h>

#define T_STEPS 2000
#define NB      1024
#define NMUL    16
#define NTH     256   // 8 warps -> 2 warps per SMSP (HW latency hiding)
#define NBLK    64    // 64*256 = 16384 threads = NB*NMUL
#define CH      16    // steps per chunk (= conv ring size = unroll)
#define NCHUNK  (T_STEPS / CH)   // 125, exact
#define PF      4     // forcing prefetch depth (~500 cyc ahead > L2 latency)

__device__ __forceinline__ float fast_lg2(float a) {
    float r;
    asm("lg2.approx.f32 %0, %1;" : "=f"(r) : "f"(a));
    return r;
}
__device__ __forceinline__ float fast_ex2(float a) {
    float r;
    asm("ex2.approx.f32 %0, %1;" : "=f"(r) : "f"(a));
    return r;
}

__global__ void __launch_bounds__(NTH, 1)
hbv_kernel(const float* __restrict__ x,      // (T, B, 3)
           const float* __restrict__ ps,     // (B, 288)
           float* __restrict__ out)          // (T, B)
{
    // per-warp transpose buffer for the m-reduction (pad 17 -> conflict-free)
    __shared__ float red[8][2][16][17];

    const int m    = threadIdx.x & (NMUL - 1);
    const int w_id = threadIdx.x >> 5;
    const int lane = threadIdx.x & 31;
    const int cell = lane >> 4;
    const int tt   = lane & 15;

    const int gwarp = blockIdx.x * 8 + w_id;
    const int b     = gwarp * 2 + cell;        // this thread's grid cell
    const int b0    = gwarp * 2;               // warp's first cell

    const float* pb = ps + b * 288 + m;

    // --- physical parameters (parRT, parAC unused by the model) ---
    const float BETA   = 1.0f   + pb[0*16]  * 5.0f;
    const float FC     = 50.0f  + pb[1*16]  * 950.0f;
    const float K0     = 0.05f  + pb[2*16]  * 0.85f;
    const float K1     = 0.01f  + pb[3*16]  * 0.49f;
    const float K2     = 0.001f + pb[4*16]  * 0.199f;
    const float LP     = 0.2f   + pb[5*16]  * 0.8f;
    const float PERC   =          pb[6*16]  * 10.0f;
    const float UZL    =          pb[7*16]  * 100.0f;
    const float TT     = -2.5f  + pb[8*16]  * 5.0f;
    const float CFMAX  = 0.5f   + pb[9*16]  * 9.5f;
    const float CFR    =          pb[10*16] * 0.1f;
    const float CWH    =          pb[11*16] * 0.2f;
    const float BETAET = 0.3f   + pb[12*16] * 4.7f;
    const float Cpar   =          pb[13*16];

    const float invFC    = 1.0f / FC;
    const float bLP      = BETAET * fast_lg2(1.0f / LP);  // BETAET*lg2(1/LP)
    const float epsF     = 1e-5f * invFC;
    const float CFRCFMAX = CFR * CFMAX;
    const float CinvFC   = Cpar * invFC;                  // for s = SLZ*C/FC

    // --- routing weights (gammaln prefactor cancels under normalization) ---
    const float aa     = fmaxf(pb[256] * 2.9f, 0.0f) + 0.1f;
    const float theta  = fmaxf(pb[272] * 6.5f, 0.0f) + 0.5f;
    const float itheta = 1.0f / theta;

    float w[CH];
    float wsum = 0.0f;
#pragma unroll
    for (int k = 0; k < 15; ++k) {
        const float tk = (float)k + 0.5f;
        w[k] = expf((aa - 1.0f) * logf(tk) - tk * itheta);
        wsum += w[k];
    }
    const float iws = 1.0f / wsum;
#pragma unroll
    for (int k = 0; k < 15; ++k) w[k] *= iws;
    w[15] = 0.0f;                         // dummy tap so ring period == unroll

    // --- state (y = SM/FC normalized; invariant y in (0,1]) ---
    float SP  = 1e-5f, MW = 1e-5f, SUZ = 1e-5f, SLZ = 1e-5f;
    float y   = epsF;

    float q[CH];
#pragma unroll
    for (int k = 0; k < CH; ++k) q[k] = 0.0f;

    // --- forcing prefetch ring: depth PF=4, register resident ---
    const float* xr = x + (size_t)b * 3;
    float Pf[PF], Tf[PF], Ef[PF];
#pragma unroll
    for (int k = 0; k < PF; ++k) {
        const float* xp = xr + (size_t)k * (NB * 3);
        Pf[k] = __ldg(xp + 0);
        Tf[k] = __ldg(xp + 1);
        Ef[k] = __ldg(xp + 2);
    }

#pragma unroll 1
    for (int c = 0; c < NCHUNK; ++c) {
#pragma unroll
        for (int j = 0; j < CH; ++j) {
            const int t = c * CH + j;
            const int s4 = j & (PF - 1);           // == t & 3 (CH multiple of PF)

            const float Pm = Pf[s4], Tc = Tf[s4], PE = Ef[s4];

            // refill slot with forcing for step t+PF (clamped; used 4 steps later)
            {
                const int tn = (t + PF < T_STEPS) ? (t + PF) : (T_STEPS - 1);
                const float* xp = xr + (size_t)tn * (NB * 3);
                Pf[s4] = __ldg(xp + 0);
                Tf[s4] = __ldg(xp + 1);
                Ef[s4] = __ldg(xp + 2);
            }

            // --- snow routine (feeds inr; runs in parallel with lg2 chain) ---
            const float rain = (Tc >= TT) ? Pm : 0.0f;
            const float snow = Pm - rain;
            const float m0 = fmaxf(CFMAX * (Tc - TT), 0.0f);       // off-chain
            const float r0 = fmaxf(CFRCFMAX * (TT - Tc), 0.0f);    // off-chain
            SP += snow;
            const float melt = fminf(m0, SP);
            MW += melt;  SP -= melt;
            const float refreeze = fminf(r0, MW);
            SP += refreeze;  MW -= refreeze;
            const float tosoil = fmaxf(fmaf(-CWH, SP, MW), 0.0f);
            MW -= tosoil;

            // --- soil routine (y = SM/FC), chain-minimized ---
            const float inr  = rain + tosoil;
            const float inrF = inr * invFC;                 // off y-chain
            const float yp   = y + inrF;                    // parallel with lg2
            const float s    = SLZ * CinvFC;                // off y-chain
            const float oms  = 1.0f - s;                    // off y-chain
            // y in (0,1], BETA>=1 -> BETA*lg2(y)<=0 -> sw in (0,1]: no clamps
            const float sw   = fast_ex2(BETA * fast_lg2(y));
            const float recharge = inr * sw;                // off y-chain
            const float y1 = fmaf(-inrF, sw, yp);           // y + inrF*(1-sw)
            const float excess = fmaxf(y1 - 1.0f, 0.0f) * FC;  // off y-chain
            const float y2 = fminf(y1, 1.0f);
            // capillary fused: y3 = y2 + s*(1-y2) = fma(y2, 1-s, s)
            const float y3 = fmaf(y2, oms, s);
            // SLZ update off the y-chain: cap = SLZ*max(C*(1-y1),0)
            const float cap = SLZ * fmaxf(fmaf(-Cpar, y1, Cpar), 0.0f);
            SLZ -= cap;
            // ef = min(y3/LP,1)^BETAET = ex2(min(BETAET*lg2(y3)+bLP, 0))
            const float ef  = fast_ex2(fminf(fmaf(fast_lg2(y3), BETAET, bLP), 0.0f));
            const float PEF = PE * invFC;                   // off y-chain
            y = fmaxf(fmaf(-PEF, ef, y3), epsF);            // fused ET + floor

            // --- response routine (parallel side-chain) ---
            SUZ += recharge + excess;
            const float PERCv = fminf(SUZ, PERC);
            SUZ -= PERCv;
            const float Q0 = K0 * fmaxf(SUZ - UZL, 0.0f);
            SUZ -= Q0;
            const float Q1 = K1 * SUZ;
            SUZ -= Q1;
            SLZ += PERCv;
            const float Q2 = K2 * SLZ;
            SLZ -= Q2;
            const float Qs = Q0 + Q1 + Q2;

            // --- routing conv: ring of 16 (renamed via unroll), 4 accumulators ---
            q[j] = Qs;
            float a0 = 0.f, a1 = 0.f, a2 = 0.f, a3 = 0.f;
#pragma unroll
            for (int k = 0; k < CH; k += 4) {
                a0 = fmaf(w[k + 0], q[(j - k - 0) & 15], a0);
                a1 = fmaf(w[k + 1], q[(j - k - 1) & 15], a1);
                a2 = fmaf(w[k + 2], q[(j - k - 2) & 15], a2);
                a3 = fmaf(w[k + 3], q[(j - k - 3) & 15], a3);
            }
            red[w_id][cell][m][j] = (a0 + a1) + (a2 + a3);  // STS: issue-only
        }

        // --- per-16-step transpose reduce over m (no per-step shuffles) ---
        __syncwarp();
        {
            float s0 = 0.f, s1 = 0.f;
#pragma unroll
            for (int mi = 0; mi < 16; mi += 2) {
                s0 += red[w_id][cell][mi + 0][tt];
                s1 += red[w_id][cell][mi + 1][tt];
            }
            out[(c * CH + tt) * NB + (b0 + cell)] = (s0 + s1) * 0.0625f;
        }
        __syncwarp();
    }
}

extern "C" void kernel_launch(void* const* d_in, const int* in_sizes, int n_in,
                              void* d_out, int out_size)
{
    const float* x  = (const float*)d_in[0];
    const float* ps = (const float*)d_in[1];
    if (n_in >= 2 && in_sizes[0] == NB * 288) {  // swapped order
        x  = (const float*)d_in[1];
        ps = (const float*)d_in[0];
    }
    float* out = (float*)d_out;
    hbv_kernel<<<NBLK, NTH>>>(x, ps, out);
}

// round 11
// speedup vs baseline: 2.2582x; 1.3045x over previous
#include <cuda_runtime.h>

#define T_STEPS 2000
#define NB      1024
#define NMUL    16
#define NTH     128   // 4 warps -> SMSPs 0..3 (1 warp/SMSP: proven optimal)
#define NBLK    128   // 128*128 = 16384 threads = NB*NMUL
#define CH      16    // steps per chunk (= conv ring size = unroll)
#define NCHUNK  (T_STEPS / CH)   // 125, exact
#define PF      4     // forcing prefetch depth
#define CSTR    336   // cell stride in red[] floats: %32==16 -> conflict-free

__device__ __forceinline__ float fast_lg2(float a) {
    float r;
    asm("lg2.approx.f32 %0, %1;" : "=f"(r) : "f"(a));
    return r;
}
__device__ __forceinline__ float fast_ex2(float a) {
    float r;
    asm("ex2.approx.f32 %0, %1;" : "=f"(r) : "f"(a));
    return r;
}

__global__ void __launch_bounds__(NTH, 1)
hbv_kernel(const float* __restrict__ x,      // (T, B, 3)
           const float* __restrict__ ps,     // (B, 288)
           float* __restrict__ out)          // (T, B)
{
    // double-buffered transpose stage: [buf][warp][cell*CSTR + t*20 + m]
    __shared__ float red[2][4][2 * CSTR];

    const int m    = threadIdx.x & (NMUL - 1);
    const int w_id = threadIdx.x >> 5;
    const int lane = threadIdx.x & 31;
    const int cell = lane >> 4;
    const int tt   = lane & 15;

    const int gwarp = blockIdx.x * 4 + w_id;
    const int b     = gwarp * 2 + cell;        // this thread's grid cell
    const int b0    = gwarp * 2;               // warp's first cell

    const float* pb = ps + b * 288 + m;

    // --- physical parameters (parRT, parAC unused by the model) ---
    const float BETA   = 1.0f   + pb[0*16]  * 5.0f;
    const float FC     = 50.0f  + pb[1*16]  * 950.0f;
    const float K0     = 0.05f  + pb[2*16]  * 0.85f;
    const float K1     = 0.01f  + pb[3*16]  * 0.49f;
    const float K2     = 0.001f + pb[4*16]  * 0.199f;
    const float LP     = 0.2f   + pb[5*16]  * 0.8f;
    const float PERC   =          pb[6*16]  * 10.0f;
    const float UZL    =          pb[7*16]  * 100.0f;
    const float TT     = -2.5f  + pb[8*16]  * 5.0f;
    const float CFMAX  = 0.5f   + pb[9*16]  * 9.5f;
    const float CFR    =          pb[10*16] * 0.1f;
    const float CWH    =          pb[11*16] * 0.2f;
    const float BETAET = 0.3f   + pb[12*16] * 4.7f;
    const float Cpar   =          pb[13*16];

    const float invFC    = 1.0f / FC;
    const float bLP      = BETAET * fast_lg2(1.0f / LP);
    const float epsF     = 1e-5f * invFC;
    const float CFRCFMAX = CFR * CFMAX;
    const float CinvFC   = Cpar * invFC;
    const float oneK1    = 1.0f - K1;
    const float oneK2    = 1.0f - K2;

    // --- routing weights (gammaln prefactor cancels under normalization) ---
    const float aa     = fmaxf(pb[256] * 2.9f, 0.0f) + 0.1f;
    const float theta  = fmaxf(pb[272] * 6.5f, 0.0f) + 0.5f;
    const float itheta = 1.0f / theta;

    float w[CH];
    float wsum = 0.0f;
#pragma unroll
    for (int k = 0; k < 15; ++k) {
        const float tk = (float)k + 0.5f;
        w[k] = expf((aa - 1.0f) * logf(tk) - tk * itheta);
        wsum += w[k];
    }
    const float iws = 1.0f / wsum;
#pragma unroll
    for (int k = 0; k < 15; ++k) w[k] *= iws;
    w[15] = 0.0f;                         // dummy tap so ring period == unroll

    // --- state (y = SM/FC normalized; invariant y in (0,1]) ---
    float SP  = 1e-5f, MW = 1e-5f, SUZ = 1e-5f, SLZ = 1e-5f;
    float y   = epsF;

    float q[CH];
#pragma unroll
    for (int k = 0; k < CH; ++k) q[k] = 0.0f;

    // --- forcing prefetch ring: depth PF=4, register resident ---
    const float* xr = x + (size_t)b * 3;
    float Pf[PF], Tf[PF], Ef[PF];
#pragma unroll
    for (int k = 0; k < PF; ++k) {
        const float* xp = xr + (size_t)k * (NB * 3);
        Pf[k] = __ldg(xp + 0);
        Tf[k] = __ldg(xp + 1);
        Ef[k] = __ldg(xp + 2);
    }

    const int rdoff = (lane >> 4) * CSTR + tt * 20;   // read base (cell_o, t_o)

#pragma unroll 1
    for (int c = 0; c < NCHUNK; ++c) {
        const int buf = c & 1;
        float* wr = &red[buf][w_id][cell * CSTR + m];

#pragma unroll
        for (int j = 0; j < CH; ++j) {
            const int t = c * CH + j;
            const int s4 = j & (PF - 1);

            const float Pm = Pf[s4], Tc = Tf[s4], PE = Ef[s4];
            {
                const int tn = (t + PF < T_STEPS) ? (t + PF) : (T_STEPS - 1);
                const float* xp = xr + (size_t)tn * (NB * 3);
                Pf[s4] = __ldg(xp + 0);
                Tf[s4] = __ldg(xp + 1);
                Ef[s4] = __ldg(xp + 2);
            }

            // --- snow routine (parallel with lg2 chain) ---
            const float rain = (Tc >= TT) ? Pm : 0.0f;
            const float snow = Pm - rain;
            const float m0 = fmaxf(CFMAX * (Tc - TT), 0.0f);
            const float r0 = fmaxf(CFRCFMAX * (TT - Tc), 0.0f);
            SP += snow;
            const float melt = fminf(m0, SP);
            MW += melt;  SP -= melt;
            const float refreeze = fminf(r0, MW);
            SP += refreeze;  MW -= refreeze;
            const float tosoil = fmaxf(fmaf(-CWH, SP, MW), 0.0f);
            MW -= tosoil;

            // --- soil routine (y = SM/FC), chain-minimized ---
            const float inr  = rain + tosoil;
            const float inrF = inr * invFC;
            const float yp   = y + inrF;
            const float s    = SLZ * CinvFC;
            const float oms  = 1.0f - s;
            const float sw   = fast_ex2(BETA * fast_lg2(y));   // <=1 by invariant
            const float recharge = inr * sw;
            const float y1 = fmaf(-inrF, sw, yp);
            const float excess = fmaxf(y1 - 1.0f, 0.0f) * FC;
            const float y2 = fminf(y1, 1.0f);
            const float y3 = fmaf(y2, oms, s);                 // capillary fused
            const float cap = SLZ * fmaxf(fmaf(-Cpar, y1, Cpar), 0.0f);
            SLZ -= cap;
            // ET with clamp moved off-chain:
            //   y' = max(y3 - PEF*min(ef',1), epsF)
            //      = max(fmaf(-PEF, ef', y3), max(y3 - PEF, epsF))
            const float ef  = fast_ex2(fmaf(fast_lg2(y3), BETAET, bLP));  // no min
            const float PEF = PE * invFC;
            const float Kfl = fmaxf(y3 - PEF, epsF);           // parallel w/ lg2/ex2
            y = fmaxf(fmaf(-PEF, ef, y3), Kfl);

            // --- response routine (side-chain, trimmed) ---
            const float SUZ1 = SUZ + recharge + excess;
            const float SUZ2 = fmaxf(SUZ1 - PERC, 0.0f);
            const float PERCv = SUZ1 - SUZ2;                   // = min(SUZ1,PERC)
            const float tq  = fmaxf(SUZ2 - UZL, 0.0f);
            const float Q0  = K0 * tq;
            const float SUZ3 = fmaf(-K0, tq, SUZ2);
            const float Q1  = K1 * SUZ3;
            SUZ = oneK1 * SUZ3;
            const float SLZ1 = SLZ + PERCv;
            const float Q2  = K2 * SLZ1;
            SLZ = oneK2 * SLZ1;
            const float Qs = Q0 + Q1 + Q2;

            // --- routing conv: ring of 16 (renamed via unroll), 4 accumulators ---
            q[j] = Qs;
            float a0 = 0.f, a1 = 0.f, a2 = 0.f, a3 = 0.f;
#pragma unroll
            for (int k = 0; k < CH; k += 4) {
                a0 = fmaf(w[k + 0], q[(j - k - 0) & 15], a0);
                a1 = fmaf(w[k + 1], q[(j - k - 1) & 15], a1);
                a2 = fmaf(w[k + 2], q[(j - k - 2) & 15], a2);
                a3 = fmaf(w[k + 3], q[(j - k - 3) & 15], a3);
            }
            wr[j * 20] = (a0 + a1) + (a2 + a3);   // STS, conflict-free
        }

        // single barrier; reads are double-buffered so they can drift into
        // the next chunk's stall shadow
        __syncwarp();
        {
            const float4* rp = (const float4*)&red[buf][w_id][rdoff];
            const float4 v0 = rp[0], v1 = rp[1], v2 = rp[2], v3 = rp[3];
            const float s01 = ((v0.x + v0.y) + (v0.z + v0.w))
                            + ((v1.x + v1.y) + (v1.z + v1.w));
            const float s23 = ((v2.x + v2.y) + (v2.z + v2.w))
                            + ((v3.x + v3.y) + (v3.z + v3.w));
            out[(c * CH + tt) * NB + (b0 + (lane >> 4))] = (s01 + s23) * 0.0625f;
        }
    }
}

extern "C" void kernel_launch(void* const* d_in, const int* in_sizes, int n_in,
                              void* d_out, int out_size)
{
    const float* x  = (const float*)d_in[0];
    const float* ps = (const float*)d_in[1];
    if (n_in >= 2 && in_sizes[0] == NB * 288) {  // swapped order
        x  = (const float*)d_in[1];
        ps = (const float*)d_in[0];
    }
    float* out = (float*)d_out;
    hbv_kernel<<<NBLK, NTH>>>(x, ps, out);
}

// round 12
// speedup vs baseline: 2.3782x; 1.0531x over previous
#include <cuda_runtime.h>

#define T_STEPS 2000
#define NB      1024
#define NMUL    16
#define NTH     128   // 4 warps -> SMSPs 0..3 (1 warp/SMSP: proven optimal)
#define NBLK    128   // 128*128 = 16384 threads = NB*NMUL
#define CH      16    // steps per chunk (= conv ring size = unroll)
#define NCHUNK  (T_STEPS / CH)   // 125, exact
#define PF      4     // forcing prefetch depth
#define CSTR    336   // cell stride in red[] floats: %32==16 -> conflict-free

__device__ __forceinline__ float fast_lg2(float a) {
    float r;
    asm("lg2.approx.f32 %0, %1;" : "=f"(r) : "f"(a));
    return r;
}
__device__ __forceinline__ float fast_ex2(float a) {
    float r;
    asm("ex2.approx.f32 %0, %1;" : "=f"(r) : "f"(a));
    return r;
}

__global__ void __launch_bounds__(NTH, 1)
hbv_kernel(const float* __restrict__ x,      // (T, B, 3)
           const float* __restrict__ ps,     // (B, 288)
           float* __restrict__ out)          // (T, B)
{
    // double-buffered transpose stage: [buf][warp][cell*CSTR + t*20 + m]
    __shared__ float red[2][4][2 * CSTR];

    const int m    = threadIdx.x & (NMUL - 1);
    const int w_id = threadIdx.x >> 5;
    const int lane = threadIdx.x & 31;
    const int cell = lane >> 4;
    const int tt   = lane & 15;

    const int gwarp = blockIdx.x * 4 + w_id;
    const int b     = gwarp * 2 + cell;
    const int b0    = gwarp * 2;

    const float* pb = ps + b * 288 + m;

    // --- physical parameters (parRT, parAC unused by the model) ---
    const float BETA   = 1.0f   + pb[0*16]  * 5.0f;
    const float FC     = 50.0f  + pb[1*16]  * 950.0f;
    const float K0     = 0.05f  + pb[2*16]  * 0.85f;
    const float K1     = 0.01f  + pb[3*16]  * 0.49f;
    const float K2     = 0.001f + pb[4*16]  * 0.199f;
    const float LP     = 0.2f   + pb[5*16]  * 0.8f;
    const float PERC   =          pb[6*16]  * 10.0f;
    const float UZL    =          pb[7*16]  * 100.0f;
    const float TT     = -2.5f  + pb[8*16]  * 5.0f;
    const float CFMAX  = 0.5f   + pb[9*16]  * 9.5f;
    const float CFR    =          pb[10*16] * 0.1f;
    const float CWH    =          pb[11*16] * 0.2f;
    const float BETAET = 0.3f   + pb[12*16] * 4.7f;
    const float Cpar   =          pb[13*16];

    const float invFC    = 1.0f / FC;
    const float bLP      = BETAET * fast_lg2(1.0f / LP);
    const float epsF     = 1e-5f * invFC;
    const float CFRCFMAX = CFR * CFMAX;
    const float CinvFC   = Cpar * invFC;
    const float oneK1    = 1.0f - K1;
    const float oneK2    = 1.0f - K2;
    const float opCWH    = 1.0f + CWH;

    // --- routing weights (gammaln prefactor cancels under normalization) ---
    const float aa     = fmaxf(pb[256] * 2.9f, 0.0f) + 0.1f;
    const float theta  = fmaxf(pb[272] * 6.5f, 0.0f) + 0.5f;
    const float itheta = 1.0f / theta;

    float w[CH];
    float wsum = 0.0f;
#pragma unroll
    for (int k = 0; k < 15; ++k) {
        const float tk = (float)k + 0.5f;
        w[k] = expf((aa - 1.0f) * logf(tk) - tk * itheta);
        wsum += w[k];
    }
    const float iws = 1.0f / wsum;
#pragma unroll
    for (int k = 0; k < 15; ++k) w[k] *= iws;
    w[15] = 0.0f;                         // dummy tap so ring period == unroll

    // --- state (y = SM/FC normalized; invariant y in (0,1]) ---
    float SP  = 1e-5f, MW = 1e-5f, SUZ = 1e-5f, SLZ = 1e-5f;
    float y   = epsF;

    float q[CH];
#pragma unroll
    for (int k = 0; k < CH; ++k) q[k] = 0.0f;

    // --- forcing prefetch ring ---
    const float* xr = x + (size_t)b * 3;
    float Pf[PF], Tf[PF], Ef[PF];
#pragma unroll
    for (int k = 0; k < PF; ++k) {
        const float* xp = xr + (size_t)k * (NB * 3);
        Pf[k] = __ldg(xp + 0);
        Tf[k] = __ldg(xp + 1);
        Ef[k] = __ldg(xp + 2);
    }

    const int rdoff = (lane >> 4) * CSTR + tt * 20;

    // one HBV body step; returns Qsim for step s
    auto do_step = [&](int s) -> float {
        const int s4 = s & (PF - 1);
        const float Pm = Pf[s4], Tc = Tf[s4], PE = Ef[s4];
        {
            const int tn = (s + PF < T_STEPS) ? (s + PF) : (T_STEPS - 1);
            const float* xp = xr + (size_t)tn * (NB * 3);
            Pf[s4] = __ldg(xp + 0);
            Tf[s4] = __ldg(xp + 1);
            Ef[s4] = __ldg(xp + 2);
        }
        // snow (reassociated: tosoil path avoids SP3/MW2 serialization)
        const float rain = (Tc >= TT) ? Pm : 0.0f;
        const float snow = Pm - rain;
        const float m0 = fmaxf(CFMAX * (Tc - TT), 0.0f);
        const float r0 = fmaxf(CFRCFMAX * (TT - Tc), 0.0f);
        const float SP1 = SP + snow;
        const float melt = fminf(m0, SP1);
        const float MW1 = MW + melt;
        const float refreeze = fminf(r0, MW1);
        const float A  = fmaf(-CWH, SP1, MW1);           // MW1 - CWH*SP1
        const float A2 = fmaf(CWH, melt, A);
        const float g  = fmaf(-opCWH, refreeze, A2);     // = MW2 - CWH*SP3
        const float tosoil = fmaxf(g, 0.0f);
        SP = SP1 - melt + refreeze;                      // off tosoil path
        MW = MW1 - refreeze - tosoil;                    // off tosoil path
        // soil (y = SM/FC)
        const float inr  = rain + tosoil;
        const float inrF = inr * invFC;
        const float sv   = SLZ * CinvFC;
        const float oms  = 1.0f - sv;
        const float sw   = fast_ex2(BETA * fast_lg2(y)); // <=1 by invariant
        const float omsw = 1.0f - sw;
        const float recharge = inr * sw;
        const float y1 = fmaf(inrF, omsw, y);            // y + inrF*(1-sw)
        const float excess = fmaxf(y1 - 1.0f, 0.0f) * FC;
        const float y2 = fminf(y1, 1.0f);
        const float y3 = fmaf(y2, oms, sv);              // capillary fused
        const float cap = SLZ * fmaxf(fmaf(-Cpar, y1, Cpar), 0.0f);
        SLZ -= cap;
        const float ef  = fast_ex2(fmaf(fast_lg2(y3), BETAET, bLP));
        const float PEF = PE * invFC;
        const float Kfl = fmaxf(y3 - PEF, epsF);         // clamp off-chain
        y = fmaxf(fmaf(-PEF, ef, y3), Kfl);
        // response
        const float SUZ1 = SUZ + recharge + excess;
        const float SUZ2 = fmaxf(SUZ1 - PERC, 0.0f);
        const float PERCv = SUZ1 - SUZ2;
        const float tq  = fmaxf(SUZ2 - UZL, 0.0f);
        const float Q0  = K0 * tq;
        const float SUZ3 = fmaf(-K0, tq, SUZ2);
        const float Q1  = K1 * SUZ3;
        SUZ = oneK1 * SUZ3;
        const float SLZ1 = SLZ + PERCv;
        const float Q2  = K2 * SLZ1;
        SLZ = oneK2 * SLZ1;
        return Q0 + Q1 + Q2;
    };

    float Qprev;  // Qsim of the previous body step (pipelined conv input)

    // conv + store for ring slot i using Qprev (fully independent fill work)
    auto do_conv = [&](int i, float* wr) {
        q[i] = Qprev;
        float a0 = 0.f, a1 = 0.f, a2 = 0.f, a3 = 0.f;
#pragma unroll
        for (int k = 0; k < CH; k += 4) {
            a0 = fmaf(w[k + 0], q[(i - k - 0) & 15], a0);
            a1 = fmaf(w[k + 1], q[(i - k - 1) & 15], a1);
            a2 = fmaf(w[k + 2], q[(i - k - 2) & 15], a2);
            a3 = fmaf(w[k + 3], q[(i - k - 3) & 15], a3);
        }
        wr[i * 20] = (a0 + a1) + (a2 + a3);   // STS, conflict-free
    };

    auto do_reduce = [&](int buf, int c) {
        const float4* rp = (const float4*)&red[buf][w_id][rdoff];
        const float4 v0 = rp[0], v1 = rp[1], v2 = rp[2], v3 = rp[3];
        const float s01 = ((v0.x + v0.y) + (v0.z + v0.w))
                        + ((v1.x + v1.y) + (v1.z + v1.w));
        const float s23 = ((v2.x + v2.y) + (v2.z + v2.w))
                        + ((v3.x + v3.y) + (v3.z + v3.w));
        out[(c * CH + tt) * NB + (b0 + (lane >> 4))] = (s01 + s23) * 0.0625f;
    };

    // peel body s = 0 (no conv yet)
    Qprev = do_step(0);

#pragma unroll 1
    for (int c = 0; c < NCHUNK - 1; ++c) {
        const int buf = c & 1;
        float* wr = &red[buf][w_id][cell * CSTR + m];
#pragma unroll
        for (int i = 0; i < CH; ++i) {
            do_conv(i, wr);                    // output t = c*16 + i (from Qprev)
            Qprev = do_step(c * CH + 1 + i);   // body s = t + 1
        }
        __syncwarp();
        do_reduce(buf, c);
    }

    // last chunk (c = 124): 15 bodies + final conv-only
    {
        const int c = NCHUNK - 1;
        const int buf = c & 1;
        float* wr = &red[buf][w_id][cell * CSTR + m];
#pragma unroll
        for (int i = 0; i < CH - 1; ++i) {
            do_conv(i, wr);
            Qprev = do_step(c * CH + 1 + i);   // s up to 1999
        }
        do_conv(CH - 1, wr);                   // output t = 1999
        __syncwarp();
        do_reduce(buf, c);
    }
}

extern "C" void kernel_launch(void* const* d_in, const int* in_sizes, int n_in,
                              void* d_out, int out_size)
{
    const float* x  = (const float*)d_in[0];
    const float* ps = (const float*)d_in[1];
    if (n_in >= 2 && in_sizes[0] == NB * 288) {  // swapped order
        x  = (const float*)d_in[1];
        ps = (const float*)d_in[0];
    }
    float* out = (float*)d_out;
    hbv_kernel<<<NBLK, NTH>>>(x, ps, out);
}